// round 1
// baseline (speedup 1.0000x reference)
#include <cuda_runtime.h>
#include <cuda_bf16.h>

// Problem constants
#define BATCH 64
#define DIM   256
#define HW    1024            // 32*32
#define NPIX  (BATCH*HW)      // 65536
#define KCODE 1024
#define M_TOT (BATCH*DIM*HW)  // 4194304 elements per image-shaped output

// Main GEMM tile config
#define BN 128                // pixels per block
#define BK 128                // codes per k-block
#define DC 32                 // d-chunk rows per E stage
#define NCHUNK 64             // (1024/128 kblocks) * (256/32 dchunks)

__device__ float g_cost[KCODE];     // 0.5*||e_k||^2
__device__ int   g_indices[NPIX];

// ---------------- packed f32x2 helpers ----------------
__device__ __forceinline__ unsigned long long pack2(float x, float y) {
    unsigned long long r;
    asm("mov.b64 %0, {%1, %2};" : "=l"(r) : "f"(x), "f"(y));
    return r;
}
__device__ __forceinline__ void unpack2(unsigned long long v, float& x, float& y) {
    asm("mov.b64 {%0, %1}, %2;" : "=f"(x), "=f"(y) : "l"(v));
}
__device__ __forceinline__ void ffma2(unsigned long long& d, unsigned long long a, unsigned long long b) {
    asm("fma.rn.f32x2 %0, %1, %2, %0;" : "+l"(d) : "l"(a), "l"(b));
}
__device__ __forceinline__ void cp_async16(void* sptr, const void* gptr) {
    unsigned saddr = (unsigned)__cvta_generic_to_shared(sptr);
    asm volatile("cp.async.cg.shared.global [%0], [%1], 16;" :: "r"(saddr), "l"(gptr));
}
__device__ __forceinline__ void cp_commit() {
    asm volatile("cp.async.commit_group;");
}
template <int N>
__device__ __forceinline__ void cp_wait() {
    asm volatile("cp.async.wait_group %0;" :: "n"(N));
}

// ---------------- kernel 1: code costs ----------------
__global__ void vq_cost_kernel(const float* __restrict__ e) {
    int k = blockIdx.x * 256 + threadIdx.x;   // 0..1023
    float s = 0.f;
    #pragma unroll 8
    for (int d = 0; d < DIM; d++) {
        float v = e[d * KCODE + k];
        s += v * v;
    }
    g_cost[k] = 0.5f * s;
}

// ---------------- kernel 2: fused GEMM + argmax ----------------
// smem: A_s [256][128] floats (32768), Ebuf 2*[32][128] (8192), cost_s (1024)
__global__ void __launch_bounds__(256, 1)
vq_argmin_kernel(const float* __restrict__ x, const float* __restrict__ e) {
    extern __shared__ float smem[];
    float* A_s    = smem;                 // 32768 floats
    float* Ebuf   = smem + 32768;         // 8192 floats (2 stages of 4096)
    float* cost_s = smem + 32768 + 8192;  // 1024 floats

    const int tid = threadIdx.x;
    const int tx = tid & 15;     // k-group
    const int ty = tid >> 4;     // n-group

    const int n0  = blockIdx.x * BN;
    const int b   = n0 >> 10;
    const int hw0 = n0 & (HW - 1);

    // Prefetch E chunk 0 (kb=0, dc=0)
    {
        const float* src = e;    // rows d=0..31, cols 0..127
        float* dst = Ebuf;
        #pragma unroll
        for (int r = 0; r < 4; r++) {
            int id = tid + r * 256;        // 0..1023
            int row = id >> 5;
            int cp  = id & 31;
            cp_async16(dst + row * BK + cp * 4, src + row * KCODE + cp * 4);
        }
        cp_commit();
    }

    // Load A panel: A_s[d][n] = x[b*DIM*HW + d*HW + hw0 + n]
    {
        const float* xA = x + (size_t)b * DIM * HW + hw0;
        #pragma unroll
        for (int r = 0; r < 32; r++) {
            int id = tid + r * 256;        // 0..8191 float4s
            int d  = id >> 5;              // 32 float4s per row
            int n4 = id & 31;
            float4 v = *reinterpret_cast<const float4*>(xA + d * HW + n4 * 4);
            *reinterpret_cast<float4*>(A_s + d * BN + n4 * 4) = v;
        }
    }
    // Load cost table
    {
        #pragma unroll
        for (int r = 0; r < 4; r++) {
            int id = tid + r * 256;
            cost_s[id] = g_cost[id];
        }
    }

    unsigned long long acc[8][4];
    float bestv[8];
    int   besti[8];
    #pragma unroll
    for (int i = 0; i < 8; i++) { bestv[i] = -3.4e38f; besti[i] = 0; }

    for (int t = 0; t < NCHUNK; t++) {
        const int kb = t >> 3;
        const int dc = t & 7;

        if (t + 1 < NCHUNK) {
            const int kb2 = (t + 1) >> 3;
            const int dc2 = (t + 1) & 7;
            const float* src = e + (dc2 * DC) * KCODE + kb2 * BK;
            float* dst = Ebuf + ((t + 1) & 1) * (DC * BK);
            #pragma unroll
            for (int r = 0; r < 4; r++) {
                int id = tid + r * 256;
                int row = id >> 5;
                int cp  = id & 31;
                cp_async16(dst + row * BK + cp * 4, src + row * KCODE + cp * 4);
            }
            cp_commit();
            cp_wait<1>();
        } else {
            cp_wait<0>();
        }
        __syncthreads();

        if (dc == 0) {
            #pragma unroll
            for (int i = 0; i < 8; i++)
                #pragma unroll
                for (int jp = 0; jp < 4; jp++)
                    acc[i][jp] = 0ULL;
        }

        // Compute: 32 d-steps over this E chunk
        const float* Eb = Ebuf + (t & 1) * (DC * BK);
        const float* Abase = A_s + (dc * DC) * BN + ty * 8;
        #pragma unroll 4
        for (int dd = 0; dd < DC; dd++) {
            float4 a0 = *reinterpret_cast<const float4*>(Abase + dd * BN);
            float4 a1 = *reinterpret_cast<const float4*>(Abase + dd * BN + 4);
            const ulonglong2* bp = reinterpret_cast<const ulonglong2*>(Eb + dd * BK + tx * 8);
            ulonglong2 b01 = bp[0];
            ulonglong2 b23 = bp[1];
            unsigned long long ap;
            ap = pack2(a0.x, a0.x); ffma2(acc[0][0], ap, b01.x); ffma2(acc[0][1], ap, b01.y); ffma2(acc[0][2], ap, b23.x); ffma2(acc[0][3], ap, b23.y);
            ap = pack2(a0.y, a0.y); ffma2(acc[1][0], ap, b01.x); ffma2(acc[1][1], ap, b01.y); ffma2(acc[1][2], ap, b23.x); ffma2(acc[1][3], ap, b23.y);
            ap = pack2(a0.z, a0.z); ffma2(acc[2][0], ap, b01.x); ffma2(acc[2][1], ap, b01.y); ffma2(acc[2][2], ap, b23.x); ffma2(acc[2][3], ap, b23.y);
            ap = pack2(a0.w, a0.w); ffma2(acc[3][0], ap, b01.x); ffma2(acc[3][1], ap, b01.y); ffma2(acc[3][2], ap, b23.x); ffma2(acc[3][3], ap, b23.y);
            ap = pack2(a1.x, a1.x); ffma2(acc[4][0], ap, b01.x); ffma2(acc[4][1], ap, b01.y); ffma2(acc[4][2], ap, b23.x); ffma2(acc[4][3], ap, b23.y);
            ap = pack2(a1.y, a1.y); ffma2(acc[5][0], ap, b01.x); ffma2(acc[5][1], ap, b01.y); ffma2(acc[5][2], ap, b23.x); ffma2(acc[5][3], ap, b23.y);
            ap = pack2(a1.z, a1.z); ffma2(acc[6][0], ap, b01.x); ffma2(acc[6][1], ap, b01.y); ffma2(acc[6][2], ap, b23.x); ffma2(acc[6][3], ap, b23.y);
            ap = pack2(a1.w, a1.w); ffma2(acc[7][0], ap, b01.x); ffma2(acc[7][1], ap, b01.y); ffma2(acc[7][2], ap, b23.x); ffma2(acc[7][3], ap, b23.y);
        }
        __syncthreads();   // protect stage buffer before next prefetch overwrite

        if (dc == 7) {
            // fold this k-block into running argmax (score = dot - 0.5||e||^2)
            const int kbase = kb * BK + tx * 8;
            float cst[8];
            #pragma unroll
            for (int j = 0; j < 8; j++) cst[j] = cost_s[kbase + j - kb * BK + kb * BK]; // cost_s[kbase+j]
            #pragma unroll
            for (int i = 0; i < 8; i++) {
                #pragma unroll
                for (int jp = 0; jp < 4; jp++) {
                    float v0, v1;
                    unpack2(acc[i][jp], v0, v1);
                    v0 -= cst[jp * 2];
                    v1 -= cst[jp * 2 + 1];
                    if (v0 > bestv[i]) { bestv[i] = v0; besti[i] = kbase + jp * 2; }
                    if (v1 > bestv[i]) { bestv[i] = v1; besti[i] = kbase + jp * 2 + 1; }
                }
            }
        }
    }

    // Cross-thread reduction over the 16 k-groups (reuse A_s region)
    __syncthreads();
    float* rv = A_s;                         // [128][16]
    int*   ri = reinterpret_cast<int*>(A_s + 2048);
    #pragma unroll
    for (int i = 0; i < 8; i++) {
        int n = ty * 8 + i;
        rv[n * 16 + tx] = bestv[i];
        ri[n * 16 + tx] = besti[i];
    }
    __syncthreads();
    if (tid < BN) {
        int n = tid;
        float bv = rv[n * 16];
        int   bi = ri[n * 16];
        #pragma unroll
        for (int c = 1; c < 16; c++) {
            float v  = rv[n * 16 + c];
            int   id = ri[n * 16 + c];
            if (v > bv || (v == bv && id < bi)) { bv = v; bi = id; }
        }
        g_indices[n0 + n] = bi;
    }
}

// ---------------- kernel 3: gather + outputs ----------------
// out layout assumed: [q_ste (M_TOT) | quantized (M_TOT) | indices (NPIX) as float]
__global__ void vq_gather_kernel(const float* __restrict__ x,
                                 const float* __restrict__ e,
                                 float* __restrict__ out, int out_size) {
    int gid = blockIdx.x * 256 + threadIdx.x;   // 0..M_TOT-1
    int hw = gid & (HW - 1);
    int c  = (gid >> 10) & (DIM - 1);
    int b  = gid >> 18;
    int n  = (b << 10) | hw;
    int idx = g_indices[n];
    float ev = __ldg(&e[c * KCODE + idx]);
    float xv = x[gid];
    float qs = xv + (ev - xv);                  // STE in reference fp32 order
    out[gid] = qs;
    if (M_TOT + gid < out_size) out[M_TOT + gid] = ev;
    if (c == 0 && 2 * M_TOT + n < out_size) out[2 * M_TOT + n] = (float)idx;
}

extern "C" void kernel_launch(void* const* d_in, const int* in_sizes, int n_in,
                              void* d_out, int out_size) {
    const float* x = (const float*)d_in[0];        // [64,256,32,32]
    const float* e = (const float*)d_in[1];        // [256,1024]
    float* out = (float*)d_out;
    (void)in_sizes; (void)n_in;

    static int smem_set = 0;
    if (!smem_set) {
        cudaFuncSetAttribute(vq_argmin_kernel,
                             cudaFuncAttributeMaxDynamicSharedMemorySize,
                             (32768 + 8192 + 1024) * sizeof(float));
        smem_set = 1;
    }

    vq_cost_kernel<<<KCODE / 256, 256>>>(e);
    vq_argmin_kernel<<<NPIX / BN, 256, (32768 + 8192 + 1024) * sizeof(float)>>>(x, e);
    vq_gather_kernel<<<M_TOT / 256, 256>>>(x, e, out, out_size);
}

// round 9
// speedup vs baseline: 1.0041x; 1.0041x over previous

#include <cuda_runtime.h>
#include <cuda_bf16.h>

// Problem constants
#define BATCH 64
#define DIM   256
#define HW    1024            // 32*32
#define NPIX  (BATCH*HW)      // 65536
#define KCODE 1024
#define M_TOT (BATCH*DIM*HW)  // 4194304 elements per image-shaped output

// Main GEMM tile config
#define BN 128                // pixels per block
#define BK 128                // codes per k-block
#define DC 32                 // d-chunk rows per E stage
#define NCHUNK 64             // (1024/128 kblocks) * (256/32 dchunks)

__device__ float g_cost[KCODE];     // 0.5*||e_k||^2
__device__ int   g_indices[NPIX];

// ---------------- packed f32x2 helpers ----------------
__device__ __forceinline__ unsigned long long pack2(float x, float y) {
    unsigned long long r;
    asm("mov.b64 %0, {%1, %2};" : "=l"(r) : "f"(x), "f"(y));
    return r;
}
__device__ __forceinline__ void unpack2(unsigned long long v, float& x, float& y) {
    asm("mov.b64 {%0, %1}, %2;" : "=f"(x), "=f"(y) : "l"(v));
}
__device__ __forceinline__ void ffma2(unsigned long long& d, unsigned long long a, unsigned long long b) {
    asm("fma.rn.f32x2 %0, %1, %2, %0;" : "+l"(d) : "l"(a), "l"(b));
}
__device__ __forceinline__ void cp_async16(void* sptr, const void* gptr) {
    unsigned saddr = (unsigned)__cvta_generic_to_shared(sptr);
    asm volatile("cp.async.cg.shared.global [%0], [%1], 16;" :: "r"(saddr), "l"(gptr));
}
__device__ __forceinline__ void cp_commit() {
    asm volatile("cp.async.commit_group;");
}
template <int N>
__device__ __forceinline__ void cp_wait() {
    asm volatile("cp.async.wait_group %0;" :: "n"(N));
}

// ---------------- kernel 1: code costs ----------------
__global__ void vq_cost_kernel(const float* __restrict__ e) {
    int k = blockIdx.x * 32 + threadIdx.x;    // <<<32, 32>>>: same per-k math as R1
    float s = 0.f;
    #pragma unroll 8
    for (int d = 0; d < DIM; d++) {
        float v = e[d * KCODE + k];
        s += v * v;
    }
    g_cost[k] = 0.5f * s;
}

// ---------------- kernel 2: fused GEMM + argmax ----------------
// smem: A_s [256][128] floats (32768), Ebuf 2*[32][128] (8192), cost_s (1024)
__global__ void __launch_bounds__(256, 1)
vq_argmin_kernel(const float* __restrict__ x, const float* __restrict__ e) {
    extern __shared__ float smem[];
    float* A_s    = smem;                 // 32768 floats
    float* Ebuf   = smem + 32768;         // 8192 floats (2 stages of 4096)
    float* cost_s = smem + 32768 + 8192;  // 1024 floats

    const int tid = threadIdx.x;
    const int tx = tid & 15;     // k-group
    const int ty = tid >> 4;     // n-group

    const int n0  = blockIdx.x * BN;
    const int b   = n0 >> 10;
    const int hw0 = n0 & (HW - 1);

    // Prefetch E chunk 0 (kb=0, dc=0)
    {
        const float* src = e;    // rows d=0..31, cols 0..127
        float* dst = Ebuf;
        #pragma unroll
        for (int r = 0; r < 4; r++) {
            int id = tid + r * 256;        // 0..1023
            int row = id >> 5;
            int cp  = id & 31;
            cp_async16(dst + row * BK + cp * 4, src + row * KCODE + cp * 4);
        }
        cp_commit();
    }

    // Load A panel: A_s[d][n] = x[b*DIM*HW + d*HW + hw0 + n]
    {
        const float* xA = x + (size_t)b * DIM * HW + hw0;
        #pragma unroll
        for (int r = 0; r < 32; r++) {
            int id = tid + r * 256;        // 0..8191 float4s
            int d  = id >> 5;              // 32 float4s per row
            int n4 = id & 31;
            float4 v = *reinterpret_cast<const float4*>(xA + d * HW + n4 * 4);
            *reinterpret_cast<float4*>(A_s + d * BN + n4 * 4) = v;
        }
    }
    // Load cost table
    {
        #pragma unroll
        for (int r = 0; r < 4; r++) {
            int id = tid + r * 256;
            cost_s[id] = g_cost[id];
        }
    }

    unsigned long long acc[8][4];
    float bestv[8];
    int   besti[8];
    #pragma unroll
    for (int i = 0; i < 8; i++) { bestv[i] = -3.4e38f; besti[i] = 0; }

    for (int t = 0; t < NCHUNK; t++) {
        const int kb = t >> 3;
        const int dc = t & 7;

        if (t + 1 < NCHUNK) {
            const int kb2 = (t + 1) >> 3;
            const int dc2 = (t + 1) & 7;
            const float* src = e + (dc2 * DC) * KCODE + kb2 * BK;
            float* dst = Ebuf + ((t + 1) & 1) * (DC * BK);
            #pragma unroll
            for (int r = 0; r < 4; r++) {
                int id = tid + r * 256;
                int row = id >> 5;
                int cp  = id & 31;
                cp_async16(dst + row * BK + cp * 4, src + row * KCODE + cp * 4);
            }
            cp_commit();
            cp_wait<1>();
        } else {
            cp_wait<0>();
        }
        __syncthreads();

        if (dc == 0) {
            #pragma unroll
            for (int i = 0; i < 8; i++)
                #pragma unroll
                for (int jp = 0; jp < 4; jp++)
                    acc[i][jp] = 0ULL;
        }

        // Compute: 32 d-steps over this E chunk
        const float* Eb = Ebuf + (t & 1) * (DC * BK);
        const float* Abase = A_s + (dc * DC) * BN + ty * 8;
        #pragma unroll 4
        for (int dd = 0; dd < DC; dd++) {
            float4 a0 = *reinterpret_cast<const float4*>(Abase + dd * BN);
            float4 a1 = *reinterpret_cast<const float4*>(Abase + dd * BN + 4);
            const ulonglong2* bp = reinterpret_cast<const ulonglong2*>(Eb + dd * BK + tx * 8);
            ulonglong2 b01 = bp[0];
            ulonglong2 b23 = bp[1];
            unsigned long long ap;
            ap = pack2(a0.x, a0.x); ffma2(acc[0][0], ap, b01.x); ffma2(acc[0][1], ap, b01.y); ffma2(acc[0][2], ap, b23.x); ffma2(acc[0][3], ap, b23.y);
            ap = pack2(a0.y, a0.y); ffma2(acc[1][0], ap, b01.x); ffma2(acc[1][1], ap, b01.y); ffma2(acc[1][2], ap, b23.x); ffma2(acc[1][3], ap, b23.y);
            ap = pack2(a0.z, a0.z); ffma2(acc[2][0], ap, b01.x); ffma2(acc[2][1], ap, b01.y); ffma2(acc[2][2], ap, b23.x); ffma2(acc[2][3], ap, b23.y);
            ap = pack2(a0.w, a0.w); ffma2(acc[3][0], ap, b01.x); ffma2(acc[3][1], ap, b01.y); ffma2(acc[3][2], ap, b23.x); ffma2(acc[3][3], ap, b23.y);
            ap = pack2(a1.x, a1.x); ffma2(acc[4][0], ap, b01.x); ffma2(acc[4][1], ap, b01.y); ffma2(acc[4][2], ap, b23.x); ffma2(acc[4][3], ap, b23.y);
            ap = pack2(a1.y, a1.y); ffma2(acc[5][0], ap, b01.x); ffma2(acc[5][1], ap, b01.y); ffma2(acc[5][2], ap, b23.x); ffma2(acc[5][3], ap, b23.y);
            ap = pack2(a1.z, a1.z); ffma2(acc[6][0], ap, b01.x); ffma2(acc[6][1], ap, b01.y); ffma2(acc[6][2], ap, b23.x); ffma2(acc[6][3], ap, b23.y);
            ap = pack2(a1.w, a1.w); ffma2(acc[7][0], ap, b01.x); ffma2(acc[7][1], ap, b01.y); ffma2(acc[7][2], ap, b23.x); ffma2(acc[7][3], ap, b23.y);
        }
        __syncthreads();   // protect stage buffer before next prefetch overwrite

        if (dc == 7) {
            // fold this k-block into running argmax (score = dot - 0.5||e||^2)
            const int kbase = kb * BK + tx * 8;
            float cst[8];
            #pragma unroll
            for (int j = 0; j < 8; j++) cst[j] = cost_s[kbase + j - kb * BK + kb * BK]; // cost_s[kbase+j]
            #pragma unroll
            for (int i = 0; i < 8; i++) {
                #pragma unroll
                for (int jp = 0; jp < 4; jp++) {
                    float v0, v1;
                    unpack2(acc[i][jp], v0, v1);
                    v0 -= cst[jp * 2];
                    v1 -= cst[jp * 2 + 1];
                    if (v0 > bestv[i]) { bestv[i] = v0; besti[i] = kbase + jp * 2; }
                    if (v1 > bestv[i]) { bestv[i] = v1; besti[i] = kbase + jp * 2 + 1; }
                }
            }
        }
    }

    // Cross-thread reduction over the 16 k-groups (reuse A_s region)
    __syncthreads();
    float* rv = A_s;                         // [128][16]
    int*   ri = reinterpret_cast<int*>(A_s + 2048);
    #pragma unroll
    for (int i = 0; i < 8; i++) {
        int n = ty * 8 + i;
        rv[n * 16 + tx] = bestv[i];
        ri[n * 16 + tx] = besti[i];
    }
    __syncthreads();
    if (tid < BN) {
        int n = tid;
        float bv = rv[n * 16];
        int   bi = ri[n * 16];
        #pragma unroll
        for (int c = 1; c < 16; c++) {
            float v  = rv[n * 16 + c];
            int   id = ri[n * 16 + c];
            if (v > bv || (v == bv && id < bi)) { bv = v; bi = id; }
        }
        g_indices[n0 + n] = bi;
    }
}

// ---------------- kernel 3: gather + outputs ----------------
// out layout assumed: [q_ste (M_TOT) | quantized (M_TOT) | indices (NPIX) as float]
__global__ void vq_gather_kernel(const float* __restrict__ x,
                                 const float* __restrict__ e,
                                 float* __restrict__ out, int out_size) {
    int gid = blockIdx.x * 256 + threadIdx.x;   // 0..M_TOT-1
    int hw = gid & (HW - 1);
    int c  = (gid >> 10) & (DIM - 1);
    int b  = gid >> 18;
    int n  = (b << 10) | hw;
    int idx = g_indices[n];
    float ev = __ldg(&e[c * KCODE + idx]);
    float xv = x[gid];
    float qs = xv + (ev - xv);                  // STE in reference fp32 order
    out[gid] = qs;
    if (M_TOT + gid < out_size) out[M_TOT + gid] = ev;
    if (c == 0 && 2 * M_TOT + n < out_size) out[2 * M_TOT + n] = (float)idx;
}

extern "C" void kernel_launch(void* const* d_in, const int* in_sizes, int n_in,
                              void* d_out, int out_size) {
    const float* x = (const float*)d_in[0];        // [64,256,32,32]
    const float* e = (const float*)d_in[1];        // [256,1024]
    float* out = (float*)d_out;
    (void)in_sizes; (void)n_in;

    static int smem_set = 0;
    if (!smem_set) {
        cudaFuncSetAttribute(vq_argmin_kernel,
                             cudaFuncAttributeMaxDynamicSharedMemorySize,
                             (32768 + 8192 + 1024) * sizeof(float));
        smem_set = 1;
    }

    vq_cost_kernel<<<KCODE / 32, 32>>>(e);
    vq_argmin_kernel<<<NPIX / BN, 256, (32768 + 8192 + 1024) * sizeof(float)>>>(x, e);
    vq_gather_kernel<<<M_TOT / 256, 256>>>(x, e, out, out_size);
}

// round 11
// speedup vs baseline: 1.0812x; 1.0768x over previous

#include <cuda_runtime.h>
#include <cuda_bf16.h>

// Problem constants
#define BATCH 64
#define DIM   256
#define HW    1024            // 32*32
#define NPIX  (BATCH*HW)      // 65536
#define KCODE 1024
#define M_TOT (BATCH*DIM*HW)  // 4194304 elements per image-shaped output

// Main GEMM tile config
#define BN 128                // pixels per block
#define BK 128                // codes per k-block
#define DC 32                 // d-chunk rows per E stage
#define NCHUNK 64             // (1024/128 kblocks) * (256/32 dchunks)

__device__ float g_cost[KCODE];     // 0.5*||e_k||^2
__device__ int   g_indices[NPIX];

// 16B-granule swizzle within a 128-float row: bijection g -> g ^ (g>>3), g in 0..31.
// Spreads the 16 B-load addresses of a warp across all 32 banks exactly 2x.
#define GSW(g) ((g) ^ ((g) >> 3))

// ---------------- packed f32x2 helpers ----------------
__device__ __forceinline__ unsigned long long pack2(float x, float y) {
    unsigned long long r;
    asm("mov.b64 %0, {%1, %2};" : "=l"(r) : "f"(x), "f"(y));
    return r;
}
__device__ __forceinline__ void unpack2(unsigned long long v, float& x, float& y) {
    asm("mov.b64 {%0, %1}, %2;" : "=f"(x), "=f"(y) : "l"(v));
}
__device__ __forceinline__ void ffma2(unsigned long long& d, unsigned long long a, unsigned long long b) {
    asm("fma.rn.f32x2 %0, %1, %2, %0;" : "+l"(d) : "l"(a), "l"(b));
}
__device__ __forceinline__ void cp_async16(void* sptr, const void* gptr) {
    unsigned saddr = (unsigned)__cvta_generic_to_shared(sptr);
    asm volatile("cp.async.cg.shared.global [%0], [%1], 16;" :: "r"(saddr), "l"(gptr));
}
__device__ __forceinline__ void cp_commit() {
    asm volatile("cp.async.commit_group;");
}
template <int N>
__device__ __forceinline__ void cp_wait() {
    asm volatile("cp.async.wait_group %0;" :: "n"(N));
}

// ---------------- kernel 1: code costs ----------------
__global__ void vq_cost_kernel(const float* __restrict__ e) {
    int k = blockIdx.x * 32 + threadIdx.x;    // <<<32, 32>>>
    float s = 0.f;
    #pragma unroll 16
    for (int d = 0; d < DIM; d++) {
        float v = e[d * KCODE + k];
        s += v * v;
    }
    g_cost[k] = 0.5f * s;
}

// ---------------- kernel 2: fused GEMM + argmax ----------------
// smem: A_s [256][128] floats (32768), Ebuf 2*[32][128] (8192), cost_s (1024)
__global__ void __launch_bounds__(256, 1)
vq_argmin_kernel(const float* __restrict__ x, const float* __restrict__ e) {
    extern __shared__ float smem[];
    float* A_s    = smem;                 // 32768 floats
    float* Ebuf   = smem + 32768;         // 8192 floats (2 stages of 4096)
    float* cost_s = smem + 32768 + 8192;  // 1024 floats

    const int tid = threadIdx.x;
    const int tx = tid & 15;     // k-group
    const int ty = tid >> 4;     // n-group

    // Swizzled byte offsets of this thread's two B granules (floats tx*8..+3, +4..+7)
    const int bo0 = GSW(2 * tx) * 4;         // float offset of granule 2tx
    const int bo1 = GSW(2 * tx + 1) * 4;     // float offset of granule 2tx+1

    const int n0  = blockIdx.x * BN;
    const int b   = n0 >> 10;
    const int hw0 = n0 & (HW - 1);

    // Prefetch E chunk 0 (kb=0, dc=0) — granule-swizzled placement
    {
        const float* src = e;    // rows d=0..31, cols 0..127
        float* dst = Ebuf;
        #pragma unroll
        for (int r = 0; r < 4; r++) {
            int id = tid + r * 256;        // 0..1023
            int row = id >> 5;
            int cp  = id & 31;
            cp_async16(dst + row * BK + GSW(cp) * 4, src + row * KCODE + cp * 4);
        }
        cp_commit();
    }

    // Load A panel: A_s[d][n] = x[b*DIM*HW + d*HW + hw0 + n]
    {
        const float* xA = x + (size_t)b * DIM * HW + hw0;
        #pragma unroll
        for (int r = 0; r < 32; r++) {
            int id = tid + r * 256;        // 0..8191 float4s
            int d  = id >> 5;              // 32 float4s per row
            int n4 = id & 31;
            float4 v = *reinterpret_cast<const float4*>(xA + d * HW + n4 * 4);
            *reinterpret_cast<float4*>(A_s + d * BN + n4 * 4) = v;
        }
    }
    // Load cost table
    {
        #pragma unroll
        for (int r = 0; r < 4; r++) {
            int id = tid + r * 256;
            cost_s[id] = g_cost[id];
        }
    }

    unsigned long long acc[8][4];
    float bestv[8];
    int   besti[8];
    #pragma unroll
    for (int i = 0; i < 8; i++) { bestv[i] = -3.4e38f; besti[i] = 0; }

    for (int t = 0; t < NCHUNK; t++) {
        const int kb = t >> 3;
        const int dc = t & 7;

        if (t + 1 < NCHUNK) {
            const int kb2 = (t + 1) >> 3;
            const int dc2 = (t + 1) & 7;
            const float* src = e + (dc2 * DC) * KCODE + kb2 * BK;
            float* dst = Ebuf + ((t + 1) & 1) * (DC * BK);
            #pragma unroll
            for (int r = 0; r < 4; r++) {
                int id = tid + r * 256;
                int row = id >> 5;
                int cp  = id & 31;
                cp_async16(dst + row * BK + GSW(cp) * 4, src + row * KCODE + cp * 4);
            }
            cp_commit();
            cp_wait<1>();
        } else {
            cp_wait<0>();
        }
        __syncthreads();

        if (dc == 0) {
            #pragma unroll
            for (int i = 0; i < 8; i++)
                #pragma unroll
                for (int jp = 0; jp < 4; jp++)
                    acc[i][jp] = 0ULL;
        }

        // Compute: 32 d-steps over this E chunk
        const float* Eb = Ebuf + (t & 1) * (DC * BK);
        const float* Abase = A_s + (dc * DC) * BN + ty * 8;
        #pragma unroll 4
        for (int dd = 0; dd < DC; dd++) {
            float4 a0 = *reinterpret_cast<const float4*>(Abase + dd * BN);
            float4 a1 = *reinterpret_cast<const float4*>(Abase + dd * BN + 4);
            // B granules via conflict-free swizzled addresses (same float values)
            ulonglong2 b01 = *reinterpret_cast<const ulonglong2*>(Eb + dd * BK + bo0);
            ulonglong2 b23 = *reinterpret_cast<const ulonglong2*>(Eb + dd * BK + bo1);
            unsigned long long ap;
            ap = pack2(a0.x, a0.x); ffma2(acc[0][0], ap, b01.x); ffma2(acc[0][1], ap, b01.y); ffma2(acc[0][2], ap, b23.x); ffma2(acc[0][3], ap, b23.y);
            ap = pack2(a0.y, a0.y); ffma2(acc[1][0], ap, b01.x); ffma2(acc[1][1], ap, b01.y); ffma2(acc[1][2], ap, b23.x); ffma2(acc[1][3], ap, b23.y);
            ap = pack2(a0.z, a0.z); ffma2(acc[2][0], ap, b01.x); ffma2(acc[2][1], ap, b01.y); ffma2(acc[2][2], ap, b23.x); ffma2(acc[2][3], ap, b23.y);
            ap = pack2(a0.w, a0.w); ffma2(acc[3][0], ap, b01.x); ffma2(acc[3][1], ap, b01.y); ffma2(acc[3][2], ap, b23.x); ffma2(acc[3][3], ap, b23.y);
            ap = pack2(a1.x, a1.x); ffma2(acc[4][0], ap, b01.x); ffma2(acc[4][1], ap, b01.y); ffma2(acc[4][2], ap, b23.x); ffma2(acc[4][3], ap, b23.y);
            ap = pack2(a1.y, a1.y); ffma2(acc[5][0], ap, b01.x); ffma2(acc[5][1], ap, b01.y); ffma2(acc[5][2], ap, b23.x); ffma2(acc[5][3], ap, b23.y);
            ap = pack2(a1.z, a1.z); ffma2(acc[6][0], ap, b01.x); ffma2(acc[6][1], ap, b01.y); ffma2(acc[6][2], ap, b23.x); ffma2(acc[6][3], ap, b23.y);
            ap = pack2(a1.w, a1.w); ffma2(acc[7][0], ap, b01.x); ffma2(acc[7][1], ap, b01.y); ffma2(acc[7][2], ap, b23.x); ffma2(acc[7][3], ap, b23.y);
        }
        __syncthreads();   // protect stage buffer before next prefetch overwrite

        if (dc == 7) {
            // fold this k-block into running argmax (score = dot - 0.5||e||^2)
            const int kbase = kb * BK + tx * 8;
            float cst[8];
            #pragma unroll
            for (int j = 0; j < 8; j++) cst[j] = cost_s[kbase + j];
            #pragma unroll
            for (int i = 0; i < 8; i++) {
                #pragma unroll
                for (int jp = 0; jp < 4; jp++) {
                    float v0, v1;
                    unpack2(acc[i][jp], v0, v1);
                    v0 -= cst[jp * 2];
                    v1 -= cst[jp * 2 + 1];
                    if (v0 > bestv[i]) { bestv[i] = v0; besti[i] = kbase + jp * 2; }
                    if (v1 > bestv[i]) { bestv[i] = v1; besti[i] = kbase + jp * 2 + 1; }
                }
            }
        }
    }

    // Cross-thread reduction over the 16 k-groups (reuse A_s region)
    __syncthreads();
    float* rv = A_s;                         // [128][16]
    int*   ri = reinterpret_cast<int*>(A_s + 2048);
    #pragma unroll
    for (int i = 0; i < 8; i++) {
        int n = ty * 8 + i;
        rv[n * 16 + tx] = bestv[i];
        ri[n * 16 + tx] = besti[i];
    }
    __syncthreads();
    if (tid < BN) {
        int n = tid;
        float bv = rv[n * 16];
        int   bi = ri[n * 16];
        #pragma unroll
        for (int c = 1; c < 16; c++) {
            float v  = rv[n * 16 + c];
            int   id = ri[n * 16 + c];
            if (v > bv || (v == bv && id < bi)) { bv = v; bi = id; }
        }
        g_indices[n0 + n] = bi;
    }
}

// ---------------- kernel 3: gather + outputs ----------------
// out layout: [q_ste (M_TOT) | quantized (M_TOT) | indices (NPIX) as float]
__global__ void vq_gather_kernel(const float* __restrict__ x,
                                 const float* __restrict__ e,
                                 float* __restrict__ out, int out_size) {
    int gid = blockIdx.x * 256 + threadIdx.x;   // 0..M_TOT-1
    int hw = gid & (HW - 1);
    int c  = (gid >> 10) & (DIM - 1);
    int b  = gid >> 18;
    int n  = (b << 10) | hw;
    int idx = g_indices[n];
    float ev = __ldg(&e[c * KCODE + idx]);
    float xv = x[gid];
    float qs = xv + (ev - xv);                  // STE in reference fp32 order
    out[gid] = qs;
    if (M_TOT + gid < out_size) out[M_TOT + gid] = ev;
    if (c == 0 && 2 * M_TOT + n < out_size) out[2 * M_TOT + n] = (float)idx;
}

extern "C" void kernel_launch(void* const* d_in, const int* in_sizes, int n_in,
                              void* d_out, int out_size) {
    const float* x = (const float*)d_in[0];        // [64,256,32,32]
    const float* e = (const float*)d_in[1];        // [256,1024]
    float* out = (float*)d_out;
    (void)in_sizes; (void)n_in;

    static int smem_set = 0;
    if (!smem_set) {
        cudaFuncSetAttribute(vq_argmin_kernel,
                             cudaFuncAttributeMaxDynamicSharedMemorySize,
                             (32768 + 8192 + 1024) * sizeof(float));
        smem_set = 1;
    }

    vq_cost_kernel<<<KCODE / 32, 32>>>(e);
    vq_argmin_kernel<<<NPIX / BN, 256, (32768 + 8192 + 1024) * sizeof(float)>>>(x, e);
    vq_gather_kernel<<<M_TOT / 256, 256>>>(x, e, out, out_size);
}

// round 12
// speedup vs baseline: 1.2692x; 1.1739x over previous

#include <cuda_runtime.h>
#include <cuda_bf16.h>

// Problem constants
#define BATCH 64
#define DIM   256
#define HW    1024            // 32*32
#define NPIX  (BATCH*HW)      // 65536
#define KCODE 1024
#define M_TOT (BATCH*DIM*HW)  // 4194304 elements per image-shaped output

// Main GEMM tile config
#define BN 128                // pixels per block
#define BK 128                // codes per k-block
#define DC 32                 // d-chunk rows per E stage
#define NCHUNK 32             // per-CTA: (512/128 kblocks) * (256/32 dchunks)

__device__ float g_cost[KCODE];     // 0.5*||e_k||^2
__device__ int   g_indices[NPIX];
__device__ float g_hbv[2 * NPIX];   // per-half best value
__device__ int   g_hbi[2 * NPIX];   // per-half best index

// 16B-granule swizzle within a 128-float row: bijection g -> g ^ (g>>3), g in 0..31.
#define GSW(g) ((g) ^ ((g) >> 3))

// ---------------- packed f32x2 helpers ----------------
__device__ __forceinline__ unsigned long long pack2(float x, float y) {
    unsigned long long r;
    asm("mov.b64 %0, {%1, %2};" : "=l"(r) : "f"(x), "f"(y));
    return r;
}
__device__ __forceinline__ void unpack2(unsigned long long v, float& x, float& y) {
    asm("mov.b64 {%0, %1}, %2;" : "=f"(x), "=f"(y) : "l"(v));
}
__device__ __forceinline__ void ffma2(unsigned long long& d, unsigned long long a, unsigned long long b) {
    asm("fma.rn.f32x2 %0, %1, %2, %0;" : "+l"(d) : "l"(a), "l"(b));
}
__device__ __forceinline__ void cp_async16(void* sptr, const void* gptr) {
    unsigned saddr = (unsigned)__cvta_generic_to_shared(sptr);
    asm volatile("cp.async.cg.shared.global [%0], [%1], 16;" :: "r"(saddr), "l"(gptr));
}
__device__ __forceinline__ void cp_commit() {
    asm volatile("cp.async.commit_group;");
}
template <int N>
__device__ __forceinline__ void cp_wait() {
    asm volatile("cp.async.wait_group %0;" :: "n"(N));
}

// ---------------- kernel 1: code costs ----------------
__global__ void vq_cost_kernel(const float* __restrict__ e) {
    int k = blockIdx.x * 32 + threadIdx.x;    // <<<32, 32>>>
    float s = 0.f;
    #pragma unroll 16
    for (int d = 0; d < DIM; d++) {
        float v = e[d * KCODE + k];
        s += v * v;
    }
    g_cost[k] = 0.5f * s;
}

// ---------------- kernel 2: fused GEMM + argmax (k-split: 512 codes/CTA) ----------------
// smem: A_s [256][128] floats (32768), Ebuf 2*[32][128] (8192), cost_s (1024)
__global__ void __launch_bounds__(256, 1)
vq_argmin_kernel(const float* __restrict__ x, const float* __restrict__ e) {
    extern __shared__ float smem[];
    float* A_s    = smem;                 // 32768 floats
    float* Ebuf   = smem + 32768;         // 8192 floats (2 stages of 4096)
    float* cost_s = smem + 32768 + 8192;  // 1024 floats

    const int tid = threadIdx.x;
    const int tx = tid & 15;     // k-group
    const int ty = tid >> 4;     // n-group

    // Swizzled float offsets of this thread's two B granules
    const int bo0 = GSW(2 * tx) * 4;
    const int bo1 = GSW(2 * tx + 1) * 4;

    const int half = blockIdx.x & 1;          // which 512-code half
    const int n0   = (blockIdx.x >> 1) * BN;
    const int b    = n0 >> 10;
    const int hw0  = n0 & (HW - 1);
    const int kb0  = half * 4;                // first global kb of this half

    // Prefetch E chunk 0 (kb=kb0, dc=0) — granule-swizzled placement
    {
        const float* src = e + kb0 * BK;
        float* dst = Ebuf;
        #pragma unroll
        for (int r = 0; r < 4; r++) {
            int id = tid + r * 256;        // 0..1023
            int row = id >> 5;
            int cp  = id & 31;
            cp_async16(dst + row * BK + GSW(cp) * 4, src + row * KCODE + cp * 4);
        }
        cp_commit();
    }

    // Load A panel: A_s[d][n] = x[b*DIM*HW + d*HW + hw0 + n]
    {
        const float* xA = x + (size_t)b * DIM * HW + hw0;
        #pragma unroll
        for (int r = 0; r < 32; r++) {
            int id = tid + r * 256;        // 0..8191 float4s
            int d  = id >> 5;              // 32 float4s per row
            int n4 = id & 31;
            float4 v = *reinterpret_cast<const float4*>(xA + d * HW + n4 * 4);
            *reinterpret_cast<float4*>(A_s + d * BN + n4 * 4) = v;
        }
    }
    // Load cost table
    {
        #pragma unroll
        for (int r = 0; r < 4; r++) {
            int id = tid + r * 256;
            cost_s[id] = g_cost[id];
        }
    }

    unsigned long long acc[8][4];
    float bestv[8];
    int   besti[8];
    #pragma unroll
    for (int i = 0; i < 8; i++) { bestv[i] = -3.4e38f; besti[i] = 0; }

    for (int t = 0; t < NCHUNK; t++) {
        const int kb = kb0 + (t >> 3);    // global kb
        const int dc = t & 7;

        if (t + 1 < NCHUNK) {
            const int kb2 = kb0 + ((t + 1) >> 3);
            const int dc2 = (t + 1) & 7;
            const float* src = e + (dc2 * DC) * KCODE + kb2 * BK;
            float* dst = Ebuf + ((t + 1) & 1) * (DC * BK);
            #pragma unroll
            for (int r = 0; r < 4; r++) {
                int id = tid + r * 256;
                int row = id >> 5;
                int cp  = id & 31;
                cp_async16(dst + row * BK + GSW(cp) * 4, src + row * KCODE + cp * 4);
            }
            cp_commit();
            cp_wait<1>();
        } else {
            cp_wait<0>();
        }
        __syncthreads();

        if (dc == 0) {
            #pragma unroll
            for (int i = 0; i < 8; i++)
                #pragma unroll
                for (int jp = 0; jp < 4; jp++)
                    acc[i][jp] = 0ULL;
        }

        // Compute: 32 d-steps over this E chunk
        const float* Eb = Ebuf + (t & 1) * (DC * BK);
        const float* Abase = A_s + (dc * DC) * BN + ty * 8;
        #pragma unroll 4
        for (int dd = 0; dd < DC; dd++) {
            float4 a0 = *reinterpret_cast<const float4*>(Abase + dd * BN);
            float4 a1 = *reinterpret_cast<const float4*>(Abase + dd * BN + 4);
            ulonglong2 b01 = *reinterpret_cast<const ulonglong2*>(Eb + dd * BK + bo0);
            ulonglong2 b23 = *reinterpret_cast<const ulonglong2*>(Eb + dd * BK + bo1);
            unsigned long long ap;
            ap = pack2(a0.x, a0.x); ffma2(acc[0][0], ap, b01.x); ffma2(acc[0][1], ap, b01.y); ffma2(acc[0][2], ap, b23.x); ffma2(acc[0][3], ap, b23.y);
            ap = pack2(a0.y, a0.y); ffma2(acc[1][0], ap, b01.x); ffma2(acc[1][1], ap, b01.y); ffma2(acc[1][2], ap, b23.x); ffma2(acc[1][3], ap, b23.y);
            ap = pack2(a0.z, a0.z); ffma2(acc[2][0], ap, b01.x); ffma2(acc[2][1], ap, b01.y); ffma2(acc[2][2], ap, b23.x); ffma2(acc[2][3], ap, b23.y);
            ap = pack2(a0.w, a0.w); ffma2(acc[3][0], ap, b01.x); ffma2(acc[3][1], ap, b01.y); ffma2(acc[3][2], ap, b23.x); ffma2(acc[3][3], ap, b23.y);
            ap = pack2(a1.x, a1.x); ffma2(acc[4][0], ap, b01.x); ffma2(acc[4][1], ap, b01.y); ffma2(acc[4][2], ap, b23.x); ffma2(acc[4][3], ap, b23.y);
            ap = pack2(a1.y, a1.y); ffma2(acc[5][0], ap, b01.x); ffma2(acc[5][1], ap, b01.y); ffma2(acc[5][2], ap, b23.x); ffma2(acc[5][3], ap, b23.y);
            ap = pack2(a1.z, a1.z); ffma2(acc[6][0], ap, b01.x); ffma2(acc[6][1], ap, b01.y); ffma2(acc[6][2], ap, b23.x); ffma2(acc[6][3], ap, b23.y);
            ap = pack2(a1.w, a1.w); ffma2(acc[7][0], ap, b01.x); ffma2(acc[7][1], ap, b01.y); ffma2(acc[7][2], ap, b23.x); ffma2(acc[7][3], ap, b23.y);
        }
        __syncthreads();   // protect stage buffer before next prefetch overwrite

        if (dc == 7) {
            // fold this k-block into running argmax (score = dot - 0.5||e||^2)
            const int kbase = kb * BK + tx * 8;
            float cst[8];
            #pragma unroll
            for (int j = 0; j < 8; j++) cst[j] = cost_s[kbase + j];
            #pragma unroll
            for (int i = 0; i < 8; i++) {
                #pragma unroll
                for (int jp = 0; jp < 4; jp++) {
                    float v0, v1;
                    unpack2(acc[i][jp], v0, v1);
                    v0 -= cst[jp * 2];
                    v1 -= cst[jp * 2 + 1];
                    if (v0 > bestv[i]) { bestv[i] = v0; besti[i] = kbase + jp * 2; }
                    if (v1 > bestv[i]) { bestv[i] = v1; besti[i] = kbase + jp * 2 + 1; }
                }
            }
        }
    }

    // Cross-thread reduction over the 16 k-groups (reuse A_s region)
    __syncthreads();
    float* rv = A_s;                         // [128][16]
    int*   ri = reinterpret_cast<int*>(A_s + 2048);
    #pragma unroll
    for (int i = 0; i < 8; i++) {
        int n = ty * 8 + i;
        rv[n * 16 + tx] = bestv[i];
        ri[n * 16 + tx] = besti[i];
    }
    __syncthreads();
    if (tid < BN) {
        int n = tid;
        float bv = rv[n * 16];
        int   bi = ri[n * 16];
        #pragma unroll
        for (int c = 1; c < 16; c++) {
            float v  = rv[n * 16 + c];
            int   id = ri[n * 16 + c];
            if (v > bv || (v == bv && id < bi)) { bv = v; bi = id; }
        }
        g_hbv[half * NPIX + n0 + n] = bv;
        g_hbi[half * NPIX + n0 + n] = bi;
    }
}

// ---------------- kernel 2b: merge the two k-halves ----------------
// half-0 indices are all < half-1 indices, so ties resolve to half-0:
// final = (v1 > v0) ? i1 : i0  — identical to the single-pass ascending scan.
__global__ void vq_merge_kernel() {
    int n = blockIdx.x * 256 + threadIdx.x;   // 0..NPIX-1
    float v0 = g_hbv[n];
    float v1 = g_hbv[NPIX + n];
    int   i0 = g_hbi[n];
    int   i1 = g_hbi[NPIX + n];
    g_indices[n] = (v1 > v0) ? i1 : i0;
}

// ---------------- kernel 3: gather + outputs (float4 vectorized) ----------------
// out layout: [q_ste (M_TOT) | quantized (M_TOT) | indices (NPIX) as float]
__global__ void vq_gather_kernel(const float* __restrict__ x,
                                 const float* __restrict__ e,
                                 float* __restrict__ out, int out_size) {
    int g4  = blockIdx.x * 256 + threadIdx.x;   // 0..M_TOT/4-1
    int gid = g4 * 4;                           // 4 consecutive hw of same (b,c)
    int hw = gid & (HW - 1);
    int c  = (gid >> 10) & (DIM - 1);
    int b  = gid >> 18;
    int n  = (b << 10) | hw;

    int i0 = g_indices[n];
    int i1 = g_indices[n + 1];
    int i2 = g_indices[n + 2];
    int i3 = g_indices[n + 3];

    const float* ec = e + c * KCODE;
    float e0 = __ldg(ec + i0);
    float e1 = __ldg(ec + i1);
    float e2 = __ldg(ec + i2);
    float e3 = __ldg(ec + i3);

    float4 xv = *reinterpret_cast<const float4*>(x + gid);
    float4 qs;
    qs.x = xv.x + (e0 - xv.x);                  // STE in reference fp32 order
    qs.y = xv.y + (e1 - xv.y);
    qs.z = xv.z + (e2 - xv.z);
    qs.w = xv.w + (e3 - xv.w);

    *reinterpret_cast<float4*>(out + gid) = qs;
    if (M_TOT + gid + 3 < out_size) {
        float4 qv = make_float4(e0, e1, e2, e3);
        *reinterpret_cast<float4*>(out + M_TOT + gid) = qv;
    }
    if (c == 0 && 2 * M_TOT + n + 3 < out_size) {
        float4 iv = make_float4((float)i0, (float)i1, (float)i2, (float)i3);
        *reinterpret_cast<float4*>(out + 2 * M_TOT + n) = iv;
    }
}

extern "C" void kernel_launch(void* const* d_in, const int* in_sizes, int n_in,
                              void* d_out, int out_size) {
    const float* x = (const float*)d_in[0];        // [64,256,32,32]
    const float* e = (const float*)d_in[1];        // [256,1024]
    float* out = (float*)d_out;
    (void)in_sizes; (void)n_in;

    static int smem_set = 0;
    if (!smem_set) {
        cudaFuncSetAttribute(vq_argmin_kernel,
                             cudaFuncAttributeMaxDynamicSharedMemorySize,
                             (32768 + 8192 + 1024) * sizeof(float));
        smem_set = 1;
    }

    vq_cost_kernel<<<KCODE / 32, 32>>>(e);
    vq_argmin_kernel<<<(NPIX / BN) * 2, 256, (32768 + 8192 + 1024) * sizeof(float)>>>(x, e);
    vq_merge_kernel<<<NPIX / 256, 256>>>();
    vq_gather_kernel<<<M_TOT / 1024, 256>>>(x, e, out, out_size);
}

// round 13
// speedup vs baseline: 1.2762x; 1.0055x over previous

#include <cuda_runtime.h>
#include <cuda_bf16.h>

// Problem constants
#define BATCH 64
#define DIM   256
#define HW    1024            // 32*32
#define NPIX  (BATCH*HW)      // 65536
#define KCODE 1024
#define M_TOT (BATCH*DIM*HW)  // 4194304 elements per image-shaped output

// Main GEMM tile config
#define BN 128                // pixels per block
#define BK 128                // codes per k-block
#define DC 32                 // d-chunk rows per E stage
#define NCHUNK 32             // per-CTA: (512/128 kblocks) * (256/32 dchunks)

__device__ float g_cost[KCODE];     // 0.5*||e_k||^2
__device__ int   g_indices[NPIX];
__device__ float g_hbv[2 * NPIX];   // per-half best value
__device__ int   g_hbi[2 * NPIX];   // per-half best index

// 16B-granule swizzle within a 128-float row: bijection g -> g ^ (g>>3), g in 0..31.
#define GSW(g) ((g) ^ ((g) >> 3))

// ---------------- packed f32x2 helpers ----------------
__device__ __forceinline__ unsigned long long pack2(float x, float y) {
    unsigned long long r;
    asm("mov.b64 %0, {%1, %2};" : "=l"(r) : "f"(x), "f"(y));
    return r;
}
__device__ __forceinline__ void unpack2(unsigned long long v, float& x, float& y) {
    asm("mov.b64 {%0, %1}, %2;" : "=f"(x), "=f"(y) : "l"(v));
}
__device__ __forceinline__ void ffma2(unsigned long long& d, unsigned long long a, unsigned long long b) {
    asm("fma.rn.f32x2 %0, %1, %2, %0;" : "+l"(d) : "l"(a), "l"(b));
}
__device__ __forceinline__ void cp_async16(void* sptr, const void* gptr) {
    unsigned saddr = (unsigned)__cvta_generic_to_shared(sptr);
    asm volatile("cp.async.cg.shared.global [%0], [%1], 16;" :: "r"(saddr), "l"(gptr));
}
__device__ __forceinline__ void cp_commit() {
    asm volatile("cp.async.commit_group;");
}
template <int N>
__device__ __forceinline__ void cp_wait() {
    asm volatile("cp.async.wait_group %0;" :: "n"(N));
}

// ---------------- kernel 1: code costs ----------------
__global__ void vq_cost_kernel(const float* __restrict__ e) {
    int k = blockIdx.x * 32 + threadIdx.x;    // <<<32, 32>>>
    float s = 0.f;
    #pragma unroll 32
    for (int d = 0; d < DIM; d++) {
        float v = e[d * KCODE + k];
        s += v * v;
    }
    g_cost[k] = 0.5f * s;
}

// ---------------- kernel 2: fused GEMM + argmax (k-split: 512 codes/CTA) ----------------
// smem: A_s [256][128] floats (32768), Ebuf 2*[32][128] (8192), cost_s (1024)
__global__ void __launch_bounds__(256, 1)
vq_argmin_kernel(const float* __restrict__ x, const float* __restrict__ e) {
    extern __shared__ float smem[];
    float* A_s    = smem;                 // 32768 floats
    float* Ebuf   = smem + 32768;         // 8192 floats (2 stages of 4096)
    float* cost_s = smem + 32768 + 8192;  // 1024 floats

    const int tid = threadIdx.x;
    const int tx = tid & 15;     // k-group
    const int ty = tid >> 4;     // n-group

    // Swizzled float offsets of this thread's two B granules
    const int bo0 = GSW(2 * tx) * 4;
    const int bo1 = GSW(2 * tx + 1) * 4;

    const int half = blockIdx.x & 1;          // which 512-code half
    const int n0   = (blockIdx.x >> 1) * BN;
    const int b    = n0 >> 10;
    const int hw0  = n0 & (HW - 1);
    const int kb0  = half * 4;                // first global kb of this half

    // Prefetch E chunk 0 (kb=kb0, dc=0) — granule-swizzled placement
    {
        const float* src = e + kb0 * BK;
        float* dst = Ebuf;
        #pragma unroll
        for (int r = 0; r < 4; r++) {
            int id = tid + r * 256;        // 0..1023
            int row = id >> 5;
            int cp  = id & 31;
            cp_async16(dst + row * BK + GSW(cp) * 4, src + row * KCODE + cp * 4);
        }
        cp_commit();
    }

    // Load A panel: A_s[d][n] = x[b*DIM*HW + d*HW + hw0 + n]
    {
        const float* xA = x + (size_t)b * DIM * HW + hw0;
        #pragma unroll
        for (int r = 0; r < 32; r++) {
            int id = tid + r * 256;        // 0..8191 float4s
            int d  = id >> 5;              // 32 float4s per row
            int n4 = id & 31;
            float4 v = *reinterpret_cast<const float4*>(xA + d * HW + n4 * 4);
            *reinterpret_cast<float4*>(A_s + d * BN + n4 * 4) = v;
        }
    }
    // Load cost table
    {
        #pragma unroll
        for (int r = 0; r < 4; r++) {
            int id = tid + r * 256;
            cost_s[id] = g_cost[id];
        }
    }

    unsigned long long acc[8][4];
    float bestv[8];
    int   besti[8];
    #pragma unroll
    for (int i = 0; i < 8; i++) { bestv[i] = -3.4e38f; besti[i] = 0; }

    for (int t = 0; t < NCHUNK; t++) {
        const int kb = kb0 + (t >> 3);    // global kb
        const int dc = t & 7;

        if (t + 1 < NCHUNK) {
            const int kb2 = kb0 + ((t + 1) >> 3);
            const int dc2 = (t + 1) & 7;
            const float* src = e + (dc2 * DC) * KCODE + kb2 * BK;
            float* dst = Ebuf + ((t + 1) & 1) * (DC * BK);
            #pragma unroll
            for (int r = 0; r < 4; r++) {
                int id = tid + r * 256;
                int row = id >> 5;
                int cp  = id & 31;
                cp_async16(dst + row * BK + GSW(cp) * 4, src + row * KCODE + cp * 4);
            }
            cp_commit();
            cp_wait<1>();
        } else {
            cp_wait<0>();
        }
        __syncthreads();

        if (dc == 0) {
            #pragma unroll
            for (int i = 0; i < 8; i++)
                #pragma unroll
                for (int jp = 0; jp < 4; jp++)
                    acc[i][jp] = 0ULL;
        }

        // Compute: 32 d-steps over this E chunk
        const float* Eb = Ebuf + (t & 1) * (DC * BK);
        const float* Abase = A_s + (dc * DC) * BN + ty * 8;
        #pragma unroll 4
        for (int dd = 0; dd < DC; dd++) {
            float4 a0 = *reinterpret_cast<const float4*>(Abase + dd * BN);
            float4 a1 = *reinterpret_cast<const float4*>(Abase + dd * BN + 4);
            ulonglong2 b01 = *reinterpret_cast<const ulonglong2*>(Eb + dd * BK + bo0);
            ulonglong2 b23 = *reinterpret_cast<const ulonglong2*>(Eb + dd * BK + bo1);
            unsigned long long ap;
            ap = pack2(a0.x, a0.x); ffma2(acc[0][0], ap, b01.x); ffma2(acc[0][1], ap, b01.y); ffma2(acc[0][2], ap, b23.x); ffma2(acc[0][3], ap, b23.y);
            ap = pack2(a0.y, a0.y); ffma2(acc[1][0], ap, b01.x); ffma2(acc[1][1], ap, b01.y); ffma2(acc[1][2], ap, b23.x); ffma2(acc[1][3], ap, b23.y);
            ap = pack2(a0.z, a0.z); ffma2(acc[2][0], ap, b01.x); ffma2(acc[2][1], ap, b01.y); ffma2(acc[2][2], ap, b23.x); ffma2(acc[2][3], ap, b23.y);
            ap = pack2(a0.w, a0.w); ffma2(acc[3][0], ap, b01.x); ffma2(acc[3][1], ap, b01.y); ffma2(acc[3][2], ap, b23.x); ffma2(acc[3][3], ap, b23.y);
            ap = pack2(a1.x, a1.x); ffma2(acc[4][0], ap, b01.x); ffma2(acc[4][1], ap, b01.y); ffma2(acc[4][2], ap, b23.x); ffma2(acc[4][3], ap, b23.y);
            ap = pack2(a1.y, a1.y); ffma2(acc[5][0], ap, b01.x); ffma2(acc[5][1], ap, b01.y); ffma2(acc[5][2], ap, b23.x); ffma2(acc[5][3], ap, b23.y);
            ap = pack2(a1.z, a1.z); ffma2(acc[6][0], ap, b01.x); ffma2(acc[6][1], ap, b01.y); ffma2(acc[6][2], ap, b23.x); ffma2(acc[6][3], ap, b23.y);
            ap = pack2(a1.w, a1.w); ffma2(acc[7][0], ap, b01.x); ffma2(acc[7][1], ap, b01.y); ffma2(acc[7][2], ap, b23.x); ffma2(acc[7][3], ap, b23.y);
        }
        __syncthreads();   // protect stage buffer before next prefetch overwrite

        if (dc == 7) {
            // fold this k-block into running argmax (score = dot - 0.5||e||^2)
            const int kbase = kb * BK + tx * 8;
            float cst[8];
            #pragma unroll
            for (int j = 0; j < 8; j++) cst[j] = cost_s[kbase + j];
            #pragma unroll
            for (int i = 0; i < 8; i++) {
                #pragma unroll
                for (int jp = 0; jp < 4; jp++) {
                    float v0, v1;
                    unpack2(acc[i][jp], v0, v1);
                    v0 -= cst[jp * 2];
                    v1 -= cst[jp * 2 + 1];
                    if (v0 > bestv[i]) { bestv[i] = v0; besti[i] = kbase + jp * 2; }
                    if (v1 > bestv[i]) { bestv[i] = v1; besti[i] = kbase + jp * 2 + 1; }
                }
            }
        }
    }

    // Cross-thread reduction over the 16 k-groups (reuse A_s region)
    __syncthreads();
    float* rv = A_s;                         // [128][16]
    int*   ri = reinterpret_cast<int*>(A_s + 2048);
    #pragma unroll
    for (int i = 0; i < 8; i++) {
        int n = ty * 8 + i;
        rv[n * 16 + tx] = bestv[i];
        ri[n * 16 + tx] = besti[i];
    }
    __syncthreads();
    if (tid < BN) {
        int n = tid;
        float bv = rv[n * 16];
        int   bi = ri[n * 16];
        #pragma unroll
        for (int c = 1; c < 16; c++) {
            float v  = rv[n * 16 + c];
            int   id = ri[n * 16 + c];
            if (v > bv || (v == bv && id < bi)) { bv = v; bi = id; }
        }
        g_hbv[half * NPIX + n0 + n] = bv;
        g_hbi[half * NPIX + n0 + n] = bi;
    }
}

// ---------------- kernel 2b: merge the two k-halves ----------------
// half-0 indices are all < half-1 indices, so ties resolve to half-0:
// final = (v1 > v0) ? i1 : i0  — identical to the single-pass ascending scan.
__global__ void vq_merge_kernel() {
    int n = blockIdx.x * 256 + threadIdx.x;   // 0..NPIX-1
    float v0 = g_hbv[n];
    float v1 = g_hbv[NPIX + n];
    int   i0 = g_hbi[n];
    int   i1 = g_hbi[NPIX + n];
    g_indices[n] = (v1 > v0) ? i1 : i0;
}

// ---------------- kernel 3: gather + outputs (smem e-row per (c,b) block) ----------------
// out layout: [q_ste (M_TOT) | quantized (M_TOT) | indices (NPIX) as float]
__global__ void __launch_bounds__(256)
vq_gather_kernel(const float* __restrict__ x,
                 const float* __restrict__ e,
                 float* __restrict__ out, int out_size) {
    __shared__ float erow[KCODE];
    const int tid = threadIdx.x;
    const int c = blockIdx.x & (DIM - 1);     // channel
    const int b = blockIdx.x >> 8;            // batch

    // load codebook row e[c][:] (coalesced, L2-hot)
    {
        const float* ec = e + (size_t)c * KCODE;
        #pragma unroll
        for (int i = 0; i < 4; i++) {
            int k4 = (tid + i * 256) * 4 / 4;  // plain index
            erow[tid + i * 256] = __ldg(ec + tid + i * 256);
            (void)k4;
        }
    }
    __syncthreads();

    const int n0   = b << 10;                 // first pixel of batch b
    const int gid0 = ((b << 8) | c) << 10;    // x/out offset of [b, c, 0]
    const int p    = tid * 4;                 // 4 consecutive hw per thread

    int4 iv4 = *reinterpret_cast<const int4*>(&g_indices[n0 + p]);
    float4 xv = *reinterpret_cast<const float4*>(x + gid0 + p);

    float e0 = erow[iv4.x];
    float e1 = erow[iv4.y];
    float e2 = erow[iv4.z];
    float e3 = erow[iv4.w];

    float4 qs;
    qs.x = xv.x + (e0 - xv.x);                // STE in reference fp32 order
    qs.y = xv.y + (e1 - xv.y);
    qs.z = xv.z + (e2 - xv.z);
    qs.w = xv.w + (e3 - xv.w);

    *reinterpret_cast<float4*>(out + gid0 + p) = qs;
    if (M_TOT + gid0 + p + 3 < out_size) {
        float4 qv = make_float4(e0, e1, e2, e3);
        *reinterpret_cast<float4*>(out + M_TOT + gid0 + p) = qv;
    }
    if (c == 0 && 2 * M_TOT + n0 + p + 3 < out_size) {
        float4 fv = make_float4((float)iv4.x, (float)iv4.y, (float)iv4.z, (float)iv4.w);
        *reinterpret_cast<float4*>(out + 2 * M_TOT + n0 + p) = fv;
    }
}

extern "C" void kernel_launch(void* const* d_in, const int* in_sizes, int n_in,
                              void* d_out, int out_size) {
    const float* x = (const float*)d_in[0];        // [64,256,32,32]
    const float* e = (const float*)d_in[1];        // [256,1024]
    float* out = (float*)d_out;
    (void)in_sizes; (void)n_in;

    static int smem_set = 0;
    if (!smem_set) {
        cudaFuncSetAttribute(vq_argmin_kernel,
                             cudaFuncAttributeMaxDynamicSharedMemorySize,
                             (32768 + 8192 + 1024) * sizeof(float));
        smem_set = 1;
    }

    vq_cost_kernel<<<KCODE / 32, 32>>>(e);
    vq_argmin_kernel<<<(NPIX / BN) * 2, 256, (32768 + 8192 + 1024) * sizeof(float)>>>(x, e);
    vq_merge_kernel<<<NPIX / 256, 256>>>();
    vq_gather_kernel<<<BATCH * DIM, 256>>>(x, e, out, out_size);
}